// round 11
// baseline (speedup 1.0000x reference)
#include <cuda_runtime.h>
#include <cuda_fp16.h>

#define TT    512
#define INSZ  512
#define HH    1024
#define OUTSZ 512
#define NG    4096
#define BSEL  63            // only batch row 63 affects the output
#define NBLK  128
#define NTHR  512

typedef unsigned long long ull;

// ---------------------------------------------------------------------------
// Static device scratch. Full h histories -> no ping-pong hazards.
// Progress via per-block flag lines (NO single-address atomics anywhere).
// ---------------------------------------------------------------------------
__device__ __align__(16) float g_h0h[TT + 1][HH];   // h0h[p+1] = h0(p)
__device__ __align__(16) float g_h1h[TT + 1][HH];   // h1h[t+1] = h1(t)
__device__ unsigned g_f0[NBLK * 32];                // L0 progress, 1 line/block
__device__ unsigned g_f1[NBLK * 32];                // L1 progress, 1 line/block
__device__ unsigned g_flags[NBLK * 32];             // init barrier flags
__device__ unsigned g_base = 0u;                    // init-barrier base
__device__ unsigned g_rep  = 0u;                    // progress base (+=TT+2/replay)

// init-only distributed grid barrier (scoped release/acquire)
__device__ __forceinline__ void gridbar(unsigned target) {
    __syncthreads();
    if (threadIdx.x == 0) {
        unsigned* f = &g_flags[blockIdx.x << 5];
        asm volatile("st.release.gpu.u32 [%0], %1;" :: "l"(f), "r"(target) : "memory");
    }
    if (threadIdx.x < NBLK) {
        unsigned* f = &g_flags[threadIdx.x << 5];
        unsigned v;
        do { asm volatile("ld.acquire.gpu.u32 %0, [%1];" : "=r"(v) : "l"(f) : "memory"); }
        while ((int)(v - target) < 0);
    }
    __syncthreads();
}

__device__ __forceinline__ void poll_flag(unsigned* f, unsigned target) {
    unsigned v;
    do { asm volatile("ld.acquire.gpu.u32 %0, [%1];" : "=r"(v) : "l"(f) : "memory"); }
    while ((int)(v - target) < 0);
}
__device__ __forceinline__ void pub_flag(unsigned* f, unsigned v) {
    asm volatile("st.release.gpu.u32 [%0], %1;" :: "l"(f), "r"(v) : "memory");
}

// packed fp32x2 FMA (sm_100+)
__device__ __forceinline__ void fma2(ull& a, ull x, ull w) {
    asm("fma.rn.f32x2 %0, %1, %2, %0;" : "+l"(a) : "l"(x), "l"(w));
}
__device__ __forceinline__ ull pk(float a, float b) {
    ull r; asm("mov.b64 %0, {%1, %2};" : "=l"(r) : "f"(a), "f"(b)); return r;
}
__device__ __forceinline__ ull h2f2(__half2 h) {
    float2 f = __half22float2(h);
    return pk(f.x, f.y);
}
__device__ __forceinline__ float upk_sum(ull a) {
    float lo, hi; asm("mov.b64 {%0, %1}, %2;" : "=f"(lo), "=f"(hi) : "l"(a));
    return lo + hi;
}
__device__ __forceinline__ float sigf_(float x) {
    return __fdividef(1.0f, 1.0f + __expf(-x));
}
__device__ __forceinline__ float tanhf_(float x) {
    return 1.0f - __fdividef(2.0f, __expf(2.0f * x) + 1.0f);
}

// shfl-reduce 4 gate partials over the warp, then the LSTM cell update.
__device__ __forceinline__ float cell_tail(ull a0, ull a1, ull a2, ull a3,
                                           float bi, float bj, float bf, float bo,
                                           float& c)
{
    float s0 = upk_sum(a0), s1 = upk_sum(a1), s2 = upk_sum(a2), s3 = upk_sum(a3);
#pragma unroll
    for (int o = 16; o; o >>= 1) {
        s0 += __shfl_xor_sync(0xffffffffu, s0, o);
        s1 += __shfl_xor_sync(0xffffffffu, s1, o);
        s2 += __shfl_xor_sync(0xffffffffu, s2, o);
        s3 += __shfl_xor_sync(0xffffffffu, s3, o);
    }
    float zi = s0 + bi, zj = s1 + bj, zf = s2 + bf + 1.0f, zo = s3 + bo;
    float cn = sigf_(zf) * c + sigf_(zi) * tanhf_(zj);
    c = cn;
    return sigf_(zo) * tanhf_(cn);
}

// SMEM (bytes): W0 fp16 [strip][k] 32x1536 | W1 fp16 32x2048 = 224 KB
#define SM_W0   0
#define SM_W1   98304
#define SM_TOT  229376

__global__ __launch_bounds__(NTHR, 1) void lstm_persistent(
    const float* __restrict__ X,
    const float* __restrict__ state,
    const float* __restrict__ W0, const float* __restrict__ b0,
    const float* __restrict__ W1, const float* __restrict__ b1,
    const float* __restrict__ Wd, const float* __restrict__ bd,
    float* __restrict__ out)
{
    extern __shared__ __align__(16) unsigned char smraw[];
    __half* w0h = (__half*)(smraw + SM_W0);
    __half* w1h = (__half*)(smraw + SM_W1);

    const int tid   = threadIdx.x;
    const int bid   = blockIdx.x;
    const int wid   = tid >> 5;
    const int lane  = tid & 31;
    const int hbase = bid << 3;
    const int jloc  = wid & 7;
    const int hcol  = hbase + jloc;

    const unsigned base = *(volatile unsigned*)&g_base;
    const unsigned rep  = *(volatile unsigned*)&g_rep;

    // ---- one-time: pack weights -> SMEM fp16, [strip c][k] ----
    for (int e = tid; e < 32 * 1536; e += NTHR) {
        int c = e & 31, k = e >> 5;
        int col = (c >> 3) * HH + hbase + (c & 7);
        w0h[c * 1536 + k] = __float2half_rn(__ldg(W0 + (size_t)k * NG + col));
    }
    for (int e = tid; e < 32 * 2048; e += NTHR) {
        int c = e & 31, k = e >> 5;
        int col = (c >> 3) * HH + hbase + (c & 7);
        w1h[c * 2048 + k] = __float2half_rn(__ldg(W1 + (size_t)k * NG + col));
    }

    // ---- per-warp registers: biases + cell state (state row 63) ----
    const float* srow = state + (size_t)BSEL * 4 * HH;
    const float* bsrc = (wid < 8) ? b0 : b1;
    float bi  = __ldg(bsrc + hcol);
    float bj  = __ldg(bsrc + HH + hcol);
    float bfv = __ldg(bsrc + 2 * HH + hcol);
    float bo  = __ldg(bsrc + 3 * HH + hcol);
    float creg = (wid < 8) ? __ldg(srow + hcol) : __ldg(srow + 2 * HH + hcol);

    if (tid < 8) {
        __stcg(&g_h0h[0][hbase + tid], __ldg(srow + HH + hbase + tid));
        __stcg(&g_h1h[0][hbase + tid], __ldg(srow + 3 * HH + hbase + tid));
    }
    gridbar(base + 1u);   // initial h0h[0]/h1h[0] globally visible

    const int c0i = jloc, c1i = 8 + jloc, c2i = 16 + jloc, c3i = 24 + jloc;
    const float* Xrow = X + (size_t)BSEL * TT * INSZ;

    if (wid < 8) {
        // =================== layer-0 chain (warps 0-7) ===================
        const __half2* s0 = (const __half2*)w0h + c0i * 768;
        const __half2* s1 = (const __half2*)w0h + c1i * 768;
        const __half2* s2 = (const __half2*)w0h + c2i * 768;
        const __half2* s3 = (const __half2*)w0h + c3i * 768;
        for (int p = 0; p < TT; p++) {
            // x-part: independent of other blocks -> overlaps producer wait
            ull a0 = 0, a1 = 0, a2 = 0, a3 = 0;
            const ull* xp = (const ull*)(Xrow + (size_t)p * INSZ);
#pragma unroll
            for (int i = 0; i < 8; i++) {
                int idx = lane + (i << 5);
                ull xv = __ldg(xp + idx);
                fma2(a0, xv, h2f2(s0[idx]));
                fma2(a1, xv, h2f2(s1[idx]));
                fma2(a2, xv, h2f2(s2[idx]));
                fma2(a3, xv, h2f2(s3[idx]));
            }
            // wait for h0(p-1) from ALL blocks: 128 distinct flag lines
            if (p > 0 && tid < NBLK) poll_flag(&g_f0[tid << 5], rep + (unsigned)p);
            asm volatile("bar.sync 1, 256;" ::: "memory");
            const ull* hp = (const ull*)g_h0h[p];
#pragma unroll
            for (int i = 0; i < 16; i++) {
                int idx = lane + (i << 5);
                ull xv = __ldcg(hp + idx);
                fma2(a0, xv, h2f2(s0[256 + idx]));
                fma2(a1, xv, h2f2(s1[256 + idx]));
                fma2(a2, xv, h2f2(s2[256 + idx]));
                fma2(a3, xv, h2f2(s3[256 + idx]));
            }
            float h = cell_tail(a0, a1, a2, a3, bi, bj, bfv, bo, creg);
            if (lane == 0) __stcg(&g_h0h[p + 1][hcol], h);
            asm volatile("bar.sync 1, 256;" ::: "memory");   // all 8 h-cols stored
            if (tid == 0) pub_flag(&g_f0[bid << 5], rep + (unsigned)p + 1u);
        }
    } else {
        // =================== layer-1 chain (warps 8-15) ==================
        const __half2* s0 = (const __half2*)w1h + c0i * 1024;
        const __half2* s1 = (const __half2*)w1h + c1i * 1024;
        const __half2* s2 = (const __half2*)w1h + c2i * 1024;
        const __half2* s3 = (const __half2*)w1h + c3i * 1024;
        for (int t = 0; t < TT; t++) {
            // wait: h0(t) from all blocks, h1(t-1) from all blocks
            if (tid - 256 < NBLK) {
                int fb = (tid - 256) << 5;
                poll_flag(&g_f0[fb], rep + (unsigned)t + 1u);
                if (t > 0) poll_flag(&g_f1[fb], rep + (unsigned)t);
            }
            asm volatile("bar.sync 2, 256;" ::: "memory");
            ull a0 = 0, a1 = 0, a2 = 0, a3 = 0;
            const ull* hp0 = (const ull*)g_h0h[t + 1];
#pragma unroll
            for (int i = 0; i < 16; i++) {
                int idx = lane + (i << 5);
                ull xv = __ldcg(hp0 + idx);
                fma2(a0, xv, h2f2(s0[idx]));
                fma2(a1, xv, h2f2(s1[idx]));
                fma2(a2, xv, h2f2(s2[idx]));
                fma2(a3, xv, h2f2(s3[idx]));
            }
            const ull* hp1 = (const ull*)g_h1h[t];
#pragma unroll
            for (int i = 0; i < 16; i++) {
                int idx = lane + (i << 5);
                ull xv = __ldcg(hp1 + idx);
                fma2(a0, xv, h2f2(s0[512 + idx]));
                fma2(a1, xv, h2f2(s1[512 + idx]));
                fma2(a2, xv, h2f2(s2[512 + idx]));
                fma2(a3, xv, h2f2(s3[512 + idx]));
            }
            float h = cell_tail(a0, a1, a2, a3, bi, bj, bfv, bo, creg);
            if (lane == 0) __stcg(&g_h1h[t + 1][hcol], h);
            asm volatile("bar.sync 2, 256;" ::: "memory");
            if (tid == 256) pub_flag(&g_f1[bid << 5], rep + (unsigned)t + 1u);
        }
    }

    // ---- global completion of layer-1 before the dense tail ----
    if (tid < NBLK) poll_flag(&g_f1[tid << 5], rep + (unsigned)TT);
    __syncthreads();

    // ---- dense: out[t][o] = h1(t) @ Wd + bd; block owns 4 t-rows ----
    {
        float* hst = (float*)smraw;          // reuse weight region (16KB)
        int t0q = bid << 2;
        for (int e = tid; e < 1024; e += NTHR)
            ((float4*)hst)[e] =
                __ldcg((const float4*)g_h1h[t0q + (e >> 8) + 1] + (e & 255));
        __syncthreads();

        int r  = tid >> 7;                   // 0..3
        int o0 = (tid & 127) << 2;           // 0..508
        float4 acc = make_float4(__ldg(bd + o0), __ldg(bd + o0 + 1),
                                 __ldg(bd + o0 + 2), __ldg(bd + o0 + 3));
        const float* hrow = hst + (r << 10);
        const float* wp = Wd + o0;
#pragma unroll 8
        for (int k = 0; k < HH; k++) {
            float4 w4 = __ldcg((const float4*)wp);
            wp += OUTSZ;
            acc.x = fmaf(hrow[k], w4.x, acc.x);
            acc.y = fmaf(hrow[k], w4.y, acc.y);
            acc.z = fmaf(hrow[k], w4.z, acc.z);
            acc.w = fmaf(hrow[k], w4.w, acc.w);
        }
        *(float4*)(out + (size_t)(t0q + r) * OUTSZ + o0) = acc;
    }

    // advance persistent bases for the next graph replay
    if (bid == 0 && tid == 0) {
        *(volatile unsigned*)&g_rep  = rep + (unsigned)(TT + 2);
        *(volatile unsigned*)&g_base = base + 2u;
    }
}

// ---------------------------------------------------------------------------
// Launcher: ONE kernel launch, 224KB dynamic smem opted in.
// ---------------------------------------------------------------------------
extern "C" void kernel_launch(void* const* d_in, const int* in_sizes, int n_in,
                              void* d_out, int out_size)
{
    (void)in_sizes; (void)n_in; (void)out_size;
    const float* X     = (const float*)d_in[0];
    const float* state = (const float*)d_in[1];
    const float* W0    = (const float*)d_in[2];
    const float* b0    = (const float*)d_in[3];
    const float* W1    = (const float*)d_in[4];
    const float* b1    = (const float*)d_in[5];
    const float* Wd    = (const float*)d_in[6];
    const float* bd    = (const float*)d_in[7];

    static int configured = 0;
    if (!configured) {
        cudaFuncSetAttribute(lstm_persistent,
                             cudaFuncAttributeMaxDynamicSharedMemorySize,
                             SM_TOT);
        configured = 1;
    }

    lstm_persistent<<<NBLK, NTHR, SM_TOT>>>(
        X, state, W0, b0, W1, b1, Wd, bd, (float*)d_out);
}